// round 1
// baseline (speedup 1.0000x reference)
#include <cuda_runtime.h>
#include <math.h>

#define BB 4
#define TT 2048
#define DIN 513
#define TO 509
#define M2 (BB*TO)       /* 2036 */
#define DM 512
#define PROJD 4096
#define LL 5
#define DSTATE 64
#define DCONV 4
#define HD 64
#define DI_ 1024
#define HH 16
#define CONVD_ 1152      /* DI + 2*DSTATE */
#define DINP 2192        /* 2*DI + 2*DSTATE + H */
#define EPSF 1e-5f

// -------------------- scratch (device globals; no runtime alloc) ------------
__device__ float g_h0[(size_t)BB*TT*DIN];     // day-transformed + xt concat
__device__ float g_h1[(size_t)M2*PROJD];      // after w1
__device__ float g_h [(size_t)M2*DM];         // residual stream
__device__ float g_hn[(size_t)M2*DM];         // LN output
__device__ float g_zx[(size_t)2*M2*DINP];     // zxbcdt per direction
__device__ float g_xbc[(size_t)2*M2*CONVD_];  // conv+silu output
__device__ float g_dt[(size_t)2*M2*HH];
__device__ float g_dA[(size_t)2*M2*HH];
__device__ float g_y [(size_t)2*M2*DI_];      // ssm output / gated-norm in-place

// -------------------- generic SGEMM: C = A[M,K] * W (+bias)(+act)(+=) -------
// TB=1: W stored [N,K] (use w.T);  TB=0: W stored [K,N]
// ACT: 0 none, 1 softsign
#define BM 128
#define BN 128
#define BKK 8

template<int TB, int ACT, int ACCUM>
__global__ __launch_bounds__(256)
void sgemm(const float* __restrict__ A, const float* __restrict__ W,
           const float* __restrict__ bias, float* __restrict__ C,
           int M, int N, int K, int lda, int ldw, int ldc,
           long sA, long sC, const int* __restrict__ widx, long sW, long sB2)
{
    int bz = blockIdx.z;
    A += (long)bz * sA;
    C += (long)bz * sC;
    if (widx) { int wi = widx[bz]; W += (long)wi * sW; bias += (long)wi * sB2; }

    __shared__ float As[BKK][BM];
    __shared__ float Ws[BKK][BN];

    int tid = threadIdx.x;
    int tx = tid & 15, ty = tid >> 4;
    int row0 = blockIdx.y * BM, col0 = blockIdx.x * BN;

    float acc[8][8];
#pragma unroll
    for (int i = 0; i < 8; i++)
#pragma unroll
        for (int j = 0; j < 8; j++) acc[i][j] = 0.f;

    for (int k0 = 0; k0 < K; k0 += BKK) {
#pragma unroll
        for (int l = 0; l < 4; l++) {
            int i = tid + l * 256;
            int r = i >> 3, c = i & 7;
            int gr = row0 + r, gk = k0 + c;
            As[c][r] = (gr < M && gk < K) ? A[(long)gr * lda + gk] : 0.f;
        }
#pragma unroll
        for (int l = 0; l < 4; l++) {
            int i = tid + l * 256;
            float v = 0.f;
            if (TB) {
                int r = i >> 3, c = i & 7;
                int gn = col0 + r, gk = k0 + c;
                if (gn < N && gk < K) v = W[(long)gn * ldw + gk];
                Ws[c][r] = v;
            } else {
                int r = i & 127, c = i >> 7;
                int gn = col0 + r, gk = k0 + c;
                if (gn < N && gk < K) v = W[(long)gk * ldw + gn];
                Ws[c][r] = v;
            }
        }
        __syncthreads();
#pragma unroll
        for (int kk = 0; kk < BKK; kk++) {
            float ar[8], br[8];
#pragma unroll
            for (int i = 0; i < 8; i++) ar[i] = As[kk][ty * 8 + i];
#pragma unroll
            for (int j = 0; j < 8; j++) br[j] = Ws[kk][tx * 8 + j];
#pragma unroll
            for (int i = 0; i < 8; i++)
#pragma unroll
                for (int j = 0; j < 8; j++)
                    acc[i][j] = fmaf(ar[i], br[j], acc[i][j]);
        }
        __syncthreads();
    }

#pragma unroll
    for (int i = 0; i < 8; i++) {
        int gr = row0 + ty * 8 + i;
        if (gr >= M) continue;
#pragma unroll
        for (int j = 0; j < 8; j++) {
            int gn = col0 + tx * 8 + j;
            if (gn >= N) continue;
            float v = acc[i][j];
            if (bias) v += bias[gn];
            if (ACT == 1) v = v / (1.f + fabsf(v));
            long ci = (long)gr * ldc + gn;
            if (ACCUM) v += C[ci];
            C[ci] = v;
        }
    }
}

// -------------------- pointwise kernels -------------------------------------
__global__ void copy_xt(const float* __restrict__ x) {
    int i = blockIdx.x * blockDim.x + threadIdx.x;
    if (i < BB * TT) g_h0[(long)i * DIN + (DIN - 1)] = x[(long)i * DIN + (DIN - 1)];
}

__global__ void ln_kernel(const float* __restrict__ w, const float* __restrict__ b) {
    int row = blockIdx.x;                 // 0..M2-1
    const float* xr = g_h + (long)row * DM;
    float* orow = g_hn + (long)row * DM;
    int tid = threadIdx.x;                // 128
    float v[4], s = 0.f, s2 = 0.f;
#pragma unroll
    for (int i = 0; i < 4; i++) { v[i] = xr[tid + i * 128]; s += v[i]; s2 += v[i] * v[i]; }
#pragma unroll
    for (int o = 16; o > 0; o >>= 1) {
        s  += __shfl_down_sync(0xffffffffu, s, o);
        s2 += __shfl_down_sync(0xffffffffu, s2, o);
    }
    __shared__ float sh[8];
    int wid = tid >> 5, lane = tid & 31;
    if (!lane) { sh[wid] = s; sh[4 + wid] = s2; }
    __syncthreads();
    if (tid == 0) {
        float ts = 0.f, t2 = 0.f;
        for (int i = 0; i < 4; i++) { ts += sh[i]; t2 += sh[4 + i]; }
        sh[0] = ts; sh[4] = t2;
    }
    __syncthreads();
    float mu = sh[0] / (float)DM;
    float var = sh[4] / (float)DM - mu * mu;
    float inv = rsqrtf(var + EPSF);
#pragma unroll
    for (int i = 0; i < 4; i++) {
        int c = tid + i * 128;
        orow[c] = (v[i] - mu) * inv * w[c] + b[c];
    }
}

// causal (dir=0) / anticausal (dir=1) depthwise conv width 4, + bias + silu
__global__ void conv_kernel(const float* __restrict__ conv_w,
                            const float* __restrict__ conv_b, int layer) {
    long idx = (long)blockIdx.x * blockDim.x + threadIdx.x;
    if (idx >= 2L * M2 * CONVD_) return;
    int c = (int)(idx % CONVD_);
    long r = idx / CONVD_;
    int dir = (int)(r / M2);
    int bt = (int)(r % M2);
    int b = bt / TO, t = bt % TO;
    int m = 2 * layer + dir;
    const float* wc = conv_w + ((long)m * CONVD_ + c) * DCONV;
    const float* zbase = g_zx + (long)dir * M2 * DINP + (long)b * TO * DINP;
    float s = conv_b[(long)m * CONVD_ + c];
#pragma unroll
    for (int j = 0; j < DCONV; j++) {
        int tt = dir ? (t + 3 - j) : (t - 3 + j);
        if (tt >= 0 && tt < TO) s += wc[j] * zbase[(long)tt * DINP + DI_ + c];
    }
    s = s / (1.f + expf(-s));  // silu
    g_xbc[(long)dir * M2 * CONVD_ + (long)bt * CONVD_ + c] = s;
}

__device__ __forceinline__ float softplusf(float x) {
    return x > 0.f ? x + log1pf(expf(-x)) : log1pf(expf(x));
}

__global__ void dt_kernel(const float* __restrict__ dtb,
                          const float* __restrict__ alog, int layer) {
    int idx = blockIdx.x * blockDim.x + threadIdx.x;
    if (idx >= 2 * M2 * HH) return;
    int h = idx % HH;
    int r = idx / HH;
    int dir = r / M2, bt = r % M2;
    int m = 2 * layer + dir;
    float raw = g_zx[((long)dir * M2 + bt) * DINP + DI_ + CONVD_ + h] + dtb[m * HH + h];
    float dt = softplusf(raw);
    float A = -expf(alog[m * HH + h]);
    g_dt[idx] = dt;
    g_dA[idx] = expf(dt * A);
}

// persistent sequential selective scan. grid (h=16, b=4, dir=2), 256 threads.
__global__ void scan_kernel(const float* __restrict__ Dp, int layer) {
    int h = blockIdx.x, b = blockIdx.y, dir = blockIdx.z;
    int m = 2 * layer + dir;
    int tid = threadIdx.x;
    int p = tid & 63, g = tid >> 6;
    float Dh = Dp[m * HH + h];

    __shared__ float sx[64], sB[64], sC[64], yr[256];
    __shared__ float sda, sdt;

    float st[16];
#pragma unroll
    for (int i = 0; i < 16; i++) st[i] = 0.f;

    const float* xbase  = g_xbc + (long)dir * M2 * CONVD_ + (long)b * TO * CONVD_;
    float*       ybase  = g_y   + (long)dir * M2 * DI_    + (long)b * TO * DI_;
    const float* dabase = g_dA  + ((long)dir * M2 + (long)b * TO) * HH;
    const float* dtbase = g_dt  + ((long)dir * M2 + (long)b * TO) * HH;

    for (int s_ = 0; s_ < TO; s_++) {
        int t = dir ? (TO - 1 - s_) : s_;
        const float* xr = xbase + (long)t * CONVD_;
        if (tid < 64)       sx[tid]       = xr[h * 64 + tid];
        else if (tid < 128) sB[tid - 64]  = xr[DI_ + (tid - 64)];
        else if (tid < 192) sC[tid - 128] = xr[DI_ + DSTATE + (tid - 128)];
        else if (tid == 192) sda = dabase[(long)t * HH + h];
        else if (tid == 193) sdt = dtbase[(long)t * HH + h];
        __syncthreads();

        float dtx = sdt * sx[p];
        float da = sda;
        float yp = 0.f;
#pragma unroll
        for (int i = 0; i < 16; i++) {
            int n = g * 16 + i;
            st[i] = st[i] * da + dtx * sB[n];
            yp += st[i] * sC[n];
        }
        yr[tid] = yp;
        __syncthreads();
        if (g == 0) {
            float y = yr[p] + yr[64 + p] + yr[128 + p] + yr[192 + p] + Dh * sx[p];
            ybase[(long)t * DI_ + h * 64 + p] = y;
        }
        __syncthreads();
    }
}

// y = rmsnorm(y * silu(z)) * norm_w, in place. grid (M2, 2), 256 threads.
__global__ void gnorm_kernel(const float* __restrict__ norm_w, int layer) {
    int row = blockIdx.x, dir = blockIdx.y;
    int m = 2 * layer + dir;
    float* yrow = g_y + ((long)dir * M2 + row) * DI_;
    const float* zrow = g_zx + ((long)dir * M2 + row) * DINP;
    int tid = threadIdx.x;
    float v[4], ss = 0.f;
#pragma unroll
    for (int i = 0; i < 4; i++) {
        int c = tid + i * 256;
        float z = zrow[c];
        float val = yrow[c] * (z / (1.f + expf(-z)));
        v[i] = val;
        ss += val * val;
    }
#pragma unroll
    for (int o = 16; o > 0; o >>= 1) ss += __shfl_down_sync(0xffffffffu, ss, o);
    __shared__ float sh[8];
    int wid = tid >> 5, lane = tid & 31;
    if (!lane) sh[wid] = ss;
    __syncthreads();
    if (tid == 0) { float tot = 0.f; for (int i = 0; i < 8; i++) tot += sh[i]; sh[0] = tot; }
    __syncthreads();
    float inv = rsqrtf(sh[0] / (float)DI_ + EPSF);
#pragma unroll
    for (int i = 0; i < 4; i++) {
        int c = tid + i * 256;
        yrow[c] = v[i] * inv * norm_w[(long)m * DI_ + c];
    }
}

// -------------------- host orchestration ------------------------------------
extern "C" void kernel_launch(void* const* d_in, const int* in_sizes, int n_in,
                              void* d_out, int out_size) {
    const float* x        = (const float*)d_in[0];
    const int*   day_idx  = (const int*)  d_in[1];
    const float* day_w    = (const float*)d_in[2];
    const float* day_b    = (const float*)d_in[3];
    const float* w1       = (const float*)d_in[4];
    const float* b1       = (const float*)d_in[5];
    const float* w2       = (const float*)d_in[6];
    const float* b2       = (const float*)d_in[7];
    const float* ln_w     = (const float*)d_in[8];
    const float* ln_b     = (const float*)d_in[9];
    const float* m_in_w   = (const float*)d_in[10];
    const float* m_conv_w = (const float*)d_in[11];
    const float* m_conv_b = (const float*)d_in[12];
    const float* m_dt     = (const float*)d_in[13];
    const float* m_Alog   = (const float*)d_in[14];
    const float* m_D      = (const float*)d_in[15];
    const float* m_norm_w = (const float*)d_in[16];
    const float* m_out_w  = (const float*)d_in[17];
    const float* out_w    = (const float*)d_in[18];
    const float* out_b    = (const float*)d_in[19];
    float* out = (float*)d_out;

    float *h0, *h1, *h, *hn, *zx, *y;
    cudaGetSymbolAddress((void**)&h0, g_h0);
    cudaGetSymbolAddress((void**)&h1, g_h1);
    cudaGetSymbolAddress((void**)&h,  g_h);
    cudaGetSymbolAddress((void**)&hn, g_hn);
    cudaGetSymbolAddress((void**)&zx, g_zx);
    cudaGetSymbolAddress((void**)&y,  g_y);

    // 1. per-batch day transform: xn @ W[day] + b[day], softsign -> g_h0[:, :, :512]
    sgemm<0, 1, 0><<<dim3(4, 16, BB), 256>>>(
        x, day_w, day_b, h0,
        TT, 512, 512, DIN, 512, DIN,
        (long)TT * DIN, (long)TT * DIN,
        day_idx, 512L * 512L, 512L);

    // 2. passthrough last channel
    copy_xt<<<(BB * TT + 255) / 256, 256>>>(x);

    // 3. patch projection: contiguous 14*513 window, stride 4*513 -> [509,4096], softsign
    sgemm<1, 1, 0><<<dim3(PROJD / BN, (TO + BM - 1) / BM, BB), 256>>>(
        h0, w1, b1, h1,
        TO, PROJD, 14 * DIN, 4 * DIN, 14 * DIN, PROJD,
        (long)TT * DIN, (long)TO * PROJD,
        nullptr, 0, 0);

    // 4. w2: [2036,4096] x [4096,512]
    sgemm<1, 0, 0><<<dim3(DM / BN, (M2 + BM - 1) / BM, 1), 256>>>(
        h1, w2, b2, h,
        M2, DM, PROJD, PROJD, PROJD, DM,
        0, 0, nullptr, 0, 0);

    // 5. layers
    for (int i = 0; i < LL; i++) {
        ln_kernel<<<M2, 128>>>(ln_w + (long)i * DM, ln_b + (long)i * DM);

        for (int d = 0; d < 2; d++) {
            int m = 2 * i + d;
            sgemm<1, 0, 0><<<dim3((DINP + BN - 1) / BN, (M2 + BM - 1) / BM, 1), 256>>>(
                hn, m_in_w + (long)m * DINP * DM, nullptr, zx + (long)d * M2 * DINP,
                M2, DINP, DM, DM, DM, DINP,
                0, 0, nullptr, 0, 0);
        }

        conv_kernel<<<(int)((2L * M2 * CONVD_ + 255) / 256), 256>>>(m_conv_w, m_conv_b, i);
        dt_kernel<<<(2 * M2 * HH + 255) / 256, 256>>>(m_dt, m_Alog, i);
        scan_kernel<<<dim3(HH, BB, 2), 256>>>(m_D, i);
        gnorm_kernel<<<dim3(M2, 2), 256>>>(m_norm_w, i);

        for (int d = 0; d < 2; d++) {
            int m = 2 * i + d;
            sgemm<1, 0, 1><<<dim3(DM / BN, (M2 + BM - 1) / BM, 1), 256>>>(
                y + (long)d * M2 * DI_, m_out_w + (long)m * DM * DI_, nullptr, h,
                M2, DM, DI_, DI_, DI_, DM,
                0, 0, nullptr, 0, 0);
        }
    }

    // 6. classifier: [2036,512] x [512,41] + bias -> d_out
    sgemm<1, 0, 0><<<dim3(1, (M2 + BM - 1) / BM, 1), 256>>>(
        h, out_w, out_b, out,
        M2, 41, DM, DM, DM, 41,
        0, 0, nullptr, 0, 0);
}

// round 3
// speedup vs baseline: 1.1309x; 1.1309x over previous
#include <cuda_runtime.h>
#include <math.h>

#define BB 4
#define TT 2048
#define DIN 513
#define TO 509
#define M2 (BB*TO)       /* 2036 */
#define DM 512
#define PROJD 4096
#define LL 5
#define DSTATE 64
#define DCONV 4
#define HD 64
#define DI_ 1024
#define HH 16
#define CONVD_ 1152      /* DI + 2*DSTATE */
#define DINP 2192        /* 2*DI + 2*DSTATE + H */
#define EPSF 1e-5f

// -------------------- scratch (device globals; no runtime alloc) ------------
__device__ float g_h0[(size_t)BB*TT*DIN];     // day-transformed + xt concat
__device__ float g_h1[(size_t)M2*PROJD];      // after w1
__device__ float g_h [(size_t)M2*DM];         // residual stream
__device__ float g_hn[(size_t)M2*DM];         // LN output
__device__ float g_zx[(size_t)2*M2*DINP];     // zxbcdt per direction
__device__ float g_xbc[(size_t)2*M2*CONVD_];  // conv+silu output
__device__ float g_dt[(size_t)2*M2*HH];
__device__ float g_dA[(size_t)2*M2*HH];
__device__ float g_y [(size_t)2*M2*DI_];      // ssm output (per-dir blocks)
__device__ float g_y2[(size_t)M2*2*DI_];      // gated-norm output, [row][dir*1024+c]

// -------------------- f32x2 helpers -----------------------------------------
__device__ __forceinline__ unsigned long long pack_dup(float a) {
    unsigned long long r;
    unsigned int au = __float_as_uint(a);
    asm("mov.b64 %0, {%1, %1};" : "=l"(r) : "r"(au));
    return r;
}
__device__ __forceinline__ void fma_x2(unsigned long long& acc,
                                       unsigned long long a, unsigned long long b) {
    asm("fma.rn.f32x2 %0, %1, %2, %0;" : "+l"(acc) : "l"(a), "l"(b));
}
__device__ __forceinline__ void unpack_x2(unsigned long long v, float& lo, float& hi) {
    unsigned int ul, uh;
    asm("mov.b64 {%0, %1}, %2;" : "=r"(ul), "=r"(uh) : "l"(v));
    lo = __uint_as_float(ul); hi = __uint_as_float(uh);
}

// -------------------- SGEMM: C = A[M,K] * W (+bias)(+act)(+=) ---------------
// TB=1: W stored [N,K];  TB=0: W stored [K,N].  ACT: 0 none, 1 softsign.
// Per-z: wi = widx ? widx[z] : z;  W += wi*sW; bias += wi*sB; A += z*sA; C += z*sC.
// kh>0: K is split across two consecutive weight blocks: gk>=kh -> W+swh, k-=kh.
template<int BM, int BN, int TM, int TN, int TB, int ACT, int ACCUM>
__global__ __launch_bounds__((BM/TM)*(BN/TN))
void sgemm(const float* __restrict__ A, const float* __restrict__ W,
           const float* __restrict__ bias, float* __restrict__ C,
           int M, int N, int K, int lda, int ldw, int ldc,
           long sA, long sC, long sW, long sB,
           const int* __restrict__ widx, int kh, long swh)
{
    constexpr int NT = (BM/TM)*(BN/TN);
    constexpr int LA = BM*8/NT;
    constexpr int LB = BN*8/NT;
    constexpr int NX = BN/TN;

    int bz = blockIdx.z;
    A += (long)bz * sA;
    C += (long)bz * sC;
    {
        int wi = widx ? widx[bz] : bz;
        W += (long)wi * sW;
        if (bias) bias += (long)wi * sB;
    }

    __shared__ __align__(16) float As[8][BM];
    __shared__ __align__(16) float Bs[8][BN];

    int tid = threadIdx.x;
    int tx = tid % NX, ty = tid / NX;
    int row0 = blockIdx.y * BM, col0 = blockIdx.x * BN;

    unsigned long long acc[TM][TN/2];
#pragma unroll
    for (int i = 0; i < TM; i++)
#pragma unroll
        for (int j = 0; j < TN/2; j++) acc[i][j] = 0ull;

    float ra[LA], rb[LB];

    auto loadG = [&](int k0) {
#pragma unroll
        for (int l = 0; l < LA; l++) {
            int i = tid + l * NT;
            int r = i >> 3, c = i & 7;
            int gr = row0 + r, gk = k0 + c;
            ra[l] = (gr < M && gk < K) ? A[(long)gr * lda + gk] : 0.f;
        }
#pragma unroll
        for (int l = 0; l < LB; l++) {
            int i = tid + l * NT;
            int r, c;
            if (TB) { r = i >> 3; c = i & 7; }
            else    { r = i & (BN - 1); c = i / BN; }
            int gn = col0 + r, gk = k0 + c;
            float v = 0.f;
            if (gn < N && gk < K) {
                const float* Wp = W;
                if (kh && gk >= kh) { Wp += swh; gk -= kh; }
                v = TB ? Wp[(long)gn * ldw + gk] : Wp[(long)gk * ldw + gn];
            }
            rb[l] = v;
        }
    };
    auto storeS = [&]() {
#pragma unroll
        for (int l = 0; l < LA; l++) {
            int i = tid + l * NT;
            As[i & 7][i >> 3] = ra[l];
        }
#pragma unroll
        for (int l = 0; l < LB; l++) {
            int i = tid + l * NT;
            if (TB) Bs[i & 7][i >> 3] = rb[l];
            else    Bs[i / BN][i & (BN - 1)] = rb[l];
        }
    };
    auto compute = [&]() {
#pragma unroll
        for (int kk = 0; kk < 8; kk++) {
            float a[TM];
            const float4* ap4 = reinterpret_cast<const float4*>(&As[kk][ty * TM]);
#pragma unroll
            for (int q = 0; q < TM/4; q++) {
                float4 t = ap4[q];
                a[4*q+0] = t.x; a[4*q+1] = t.y; a[4*q+2] = t.z; a[4*q+3] = t.w;
            }
            unsigned long long bp[TN/2];
            const ulonglong2* bp2 = reinterpret_cast<const ulonglong2*>(&Bs[kk][tx * TN]);
#pragma unroll
            for (int q = 0; q < TN/4; q++) {
                ulonglong2 t = bp2[q];
                bp[2*q] = t.x; bp[2*q+1] = t.y;
            }
#pragma unroll
            for (int i = 0; i < TM; i++) {
                unsigned long long ap = pack_dup(a[i]);
#pragma unroll
                for (int j = 0; j < TN/2; j++) fma_x2(acc[i][j], ap, bp[j]);
            }
        }
    };

    loadG(0);
    storeS();
    __syncthreads();
    for (int k0 = 8; k0 < K; k0 += 8) {
        loadG(k0);
        compute();
        __syncthreads();
        storeS();
        __syncthreads();
    }
    compute();

#pragma unroll
    for (int i = 0; i < TM; i++) {
        int gr = row0 + ty * TM + i;
        if (gr >= M) continue;
#pragma unroll
        for (int j = 0; j < TN/2; j++) {
            float v0, v1;
            unpack_x2(acc[i][j], v0, v1);
            int gn0 = col0 + tx * TN + 2*j;
#pragma unroll
            for (int e = 0; e < 2; e++) {
                int gn = gn0 + e;
                if (gn >= N) continue;
                float v = e ? v1 : v0;
                if (bias) v += bias[gn];
                if (ACT == 1) v = v / (1.f + fabsf(v));
                long ci = (long)gr * ldc + gn;
                if (ACCUM) v += C[ci];
                C[ci] = v;
            }
        }
    }
}

// -------------------- pointwise kernels -------------------------------------
__global__ void copy_xt(const float* __restrict__ x) {
    int i = blockIdx.x * blockDim.x + threadIdx.x;
    if (i < BB * TT) g_h0[(long)i * DIN + (DIN - 1)] = x[(long)i * DIN + (DIN - 1)];
}

__global__ void ln_kernel(const float* __restrict__ w, const float* __restrict__ b) {
    int row = blockIdx.x;
    const float* xr = g_h + (long)row * DM;
    float* orow = g_hn + (long)row * DM;
    int tid = threadIdx.x;                // 128
    float v[4], s = 0.f, s2 = 0.f;
#pragma unroll
    for (int i = 0; i < 4; i++) { v[i] = xr[tid + i * 128]; s += v[i]; s2 += v[i] * v[i]; }
#pragma unroll
    for (int o = 16; o > 0; o >>= 1) {
        s  += __shfl_down_sync(0xffffffffu, s, o);
        s2 += __shfl_down_sync(0xffffffffu, s2, o);
    }
    __shared__ float sh[8];
    int wid = tid >> 5, lane = tid & 31;
    if (!lane) { sh[wid] = s; sh[4 + wid] = s2; }
    __syncthreads();
    if (tid == 0) {
        float ts = 0.f, t2 = 0.f;
        for (int i = 0; i < 4; i++) { ts += sh[i]; t2 += sh[4 + i]; }
        sh[0] = ts; sh[4] = t2;
    }
    __syncthreads();
    float mu = sh[0] / (float)DM;
    float var = sh[4] / (float)DM - mu * mu;
    float inv = rsqrtf(var + EPSF);
#pragma unroll
    for (int i = 0; i < 4; i++) {
        int c = tid + i * 128;
        orow[c] = (v[i] - mu) * inv * w[c] + b[c];
    }
}

__global__ void conv_kernel(const float* __restrict__ conv_w,
                            const float* __restrict__ conv_b, int layer) {
    long idx = (long)blockIdx.x * blockDim.x + threadIdx.x;
    if (idx >= 2L * M2 * CONVD_) return;
    int c = (int)(idx % CONVD_);
    long r = idx / CONVD_;
    int dir = (int)(r / M2);
    int bt = (int)(r % M2);
    int b = bt / TO, t = bt % TO;
    int m = 2 * layer + dir;
    const float* wc = conv_w + ((long)m * CONVD_ + c) * DCONV;
    const float* zbase = g_zx + (long)dir * M2 * DINP + (long)b * TO * DINP;
    float s = conv_b[(long)m * CONVD_ + c];
#pragma unroll
    for (int j = 0; j < DCONV; j++) {
        int tt = dir ? (t + 3 - j) : (t - 3 + j);
        if (tt >= 0 && tt < TO) s += wc[j] * zbase[(long)tt * DINP + DI_ + c];
    }
    s = s / (1.f + expf(-s));  // silu
    g_xbc[(long)dir * M2 * CONVD_ + (long)bt * CONVD_ + c] = s;
}

__device__ __forceinline__ float softplusf(float x) {
    return x > 0.f ? x + log1pf(expf(-x)) : log1pf(expf(x));
}

__global__ void dt_kernel(const float* __restrict__ dtb,
                          const float* __restrict__ alog, int layer) {
    int idx = blockIdx.x * blockDim.x + threadIdx.x;
    if (idx >= 2 * M2 * HH) return;
    int h = idx % HH;
    int r = idx / HH;
    int dir = r / M2, bt = r % M2;
    int m = 2 * layer + dir;
    float raw = g_zx[((long)dir * M2 + bt) * DINP + DI_ + CONVD_ + h] + dtb[m * HH + h];
    float dt = softplusf(raw);
    float A = -expf(alog[m * HH + h]);
    g_dt[idx] = dt;
    g_dA[idx] = expf(dt * A);
}

// persistent sequential selective scan. grid (h=16, b=4, dir=2), 256 threads.
__global__ void scan_kernel(const float* __restrict__ Dp, int layer) {
    int h = blockIdx.x, b = blockIdx.y, dir = blockIdx.z;
    int m = 2 * layer + dir;
    int tid = threadIdx.x;
    int p = tid & 63, g = tid >> 6;
    float Dh = Dp[m * HH + h];

    __shared__ float sx[64], sB[64], sC[64], yr[256];
    __shared__ float sda, sdt;

    float st[16];
#pragma unroll
    for (int i = 0; i < 16; i++) st[i] = 0.f;

    const float* xbase  = g_xbc + (long)dir * M2 * CONVD_ + (long)b * TO * CONVD_;
    float*       ybase  = g_y   + (long)dir * M2 * DI_    + (long)b * TO * DI_;
    const float* dabase = g_dA  + ((long)dir * M2 + (long)b * TO) * HH;
    const float* dtbase = g_dt  + ((long)dir * M2 + (long)b * TO) * HH;

    for (int s_ = 0; s_ < TO; s_++) {
        int t = dir ? (TO - 1 - s_) : s_;
        const float* xr = xbase + (long)t * CONVD_;
        if (tid < 64)       sx[tid]       = xr[h * 64 + tid];
        else if (tid < 128) sB[tid - 64]  = xr[DI_ + (tid - 64)];
        else if (tid < 192) sC[tid - 128] = xr[DI_ + DSTATE + (tid - 128)];
        else if (tid == 192) sda = dabase[(long)t * HH + h];
        else if (tid == 193) sdt = dtbase[(long)t * HH + h];
        __syncthreads();

        float dtx = sdt * sx[p];
        float da = sda;
        float yp = 0.f;
#pragma unroll
        for (int i = 0; i < 16; i++) {
            int n = g * 16 + i;
            st[i] = st[i] * da + dtx * sB[n];
            yp += st[i] * sC[n];
        }
        yr[tid] = yp;
        __syncthreads();
        if (g == 0) {
            float y = yr[p] + yr[64 + p] + yr[128 + p] + yr[192 + p] + Dh * sx[p];
            ybase[(long)t * DI_ + h * 64 + p] = y;
        }
        __syncthreads();
    }
}

// y2[row][dir*1024+c] = rmsnorm(y * silu(z)) * norm_w. grid (M2, 2), 256 thr.
__global__ void gnorm_kernel(const float* __restrict__ norm_w, int layer) {
    int row = blockIdx.x, dir = blockIdx.y;
    int m = 2 * layer + dir;
    const float* yrow = g_y + ((long)dir * M2 + row) * DI_;
    const float* zrow = g_zx + ((long)dir * M2 + row) * DINP;
    float* orow = g_y2 + (long)row * (2 * DI_) + (long)dir * DI_;
    int tid = threadIdx.x;
    float v[4], ss = 0.f;
#pragma unroll
    for (int i = 0; i < 4; i++) {
        int c = tid + i * 256;
        float z = zrow[c];
        float val = yrow[c] * (z / (1.f + expf(-z)));
        v[i] = val;
        ss += val * val;
    }
#pragma unroll
    for (int o = 16; o > 0; o >>= 1) ss += __shfl_down_sync(0xffffffffu, ss, o);
    __shared__ float sh[8];
    int wid = tid >> 5, lane = tid & 31;
    if (!lane) sh[wid] = ss;
    __syncthreads();
    if (tid == 0) { float tot = 0.f; for (int i = 0; i < 8; i++) tot += sh[i]; sh[0] = tot; }
    __syncthreads();
    float inv = rsqrtf(sh[0] / (float)DI_ + EPSF);
#pragma unroll
    for (int i = 0; i < 4; i++) {
        int c = tid + i * 256;
        orow[c] = v[i] * inv * norm_w[(long)m * DI_ + c];
    }
}

// -------------------- host orchestration ------------------------------------
extern "C" void kernel_launch(void* const* d_in, const int* in_sizes, int n_in,
                              void* d_out, int out_size) {
    const float* x        = (const float*)d_in[0];
    const int*   day_idx  = (const int*)  d_in[1];
    const float* day_w    = (const float*)d_in[2];
    const float* day_b    = (const float*)d_in[3];
    const float* w1       = (const float*)d_in[4];
    const float* b1       = (const float*)d_in[5];
    const float* w2       = (const float*)d_in[6];
    const float* b2       = (const float*)d_in[7];
    const float* ln_w     = (const float*)d_in[8];
    const float* ln_b     = (const float*)d_in[9];
    const float* m_in_w   = (const float*)d_in[10];
    const float* m_conv_w = (const float*)d_in[11];
    const float* m_conv_b = (const float*)d_in[12];
    const float* m_dt     = (const float*)d_in[13];
    const float* m_Alog   = (const float*)d_in[14];
    const float* m_D      = (const float*)d_in[15];
    const float* m_norm_w = (const float*)d_in[16];
    const float* m_out_w  = (const float*)d_in[17];
    const float* out_w    = (const float*)d_in[18];
    const float* out_b    = (const float*)d_in[19];
    float* out = (float*)d_out;

    float *h0, *h1, *h, *hn, *zx, *y2;
    cudaGetSymbolAddress((void**)&h0, g_h0);
    cudaGetSymbolAddress((void**)&h1, g_h1);
    cudaGetSymbolAddress((void**)&h,  g_h);
    cudaGetSymbolAddress((void**)&hn, g_hn);
    cudaGetSymbolAddress((void**)&zx, g_zx);
    cudaGetSymbolAddress((void**)&y2, g_y2);

    // 1. per-batch day transform (softsign) -> g_h0[:, :, :512]
    sgemm<128,128,8,8, 0,1,0><<<dim3(4, 16, BB), 256>>>(
        x, day_w, day_b, h0,
        TT, 512, 512, DIN, 512, DIN,
        (long)TT * DIN, (long)TT * DIN, 512L * 512L, 512L,
        day_idx, 0, 0);

    // 2. passthrough last channel
    copy_xt<<<(BB * TT + 255) / 256, 256>>>(x);

    // 3. patch projection (contiguous window) -> [509,4096], softsign
    sgemm<128,128,8,8, 1,1,0><<<dim3(PROJD / 128, (TO + 127) / 128, BB), 256>>>(
        h0, w1, b1, h1,
        TO, PROJD, 14 * DIN, 4 * DIN, 14 * DIN, PROJD,
        (long)TT * DIN, (long)TO * PROJD, 0, 0,
        nullptr, 0, 0);

    // 4. w2: [2036,4096] x [4096,512]  (64x64 tiles -> 256 blocks)
    sgemm<64,64,4,4, 1,0,0><<<dim3(DM / 64, (M2 + 63) / 64, 1), 256>>>(
        h1, w2, b2, h,
        M2, DM, PROJD, PROJD, PROJD, DM,
        0, 0, 0, 0, nullptr, 0, 0);

    // 5. layers
    for (int i = 0; i < LL; i++) {
        ln_kernel<<<M2, 128>>>(ln_w + (long)i * DM, ln_b + (long)i * DM);

        // in_proj, both directions batched (z selects weight + output block)
        sgemm<128,128,8,8, 1,0,0><<<dim3((DINP + 127) / 128, (M2 + 127) / 128, 2), 256>>>(
            hn, m_in_w + (long)(2 * i) * DINP * DM, nullptr, zx,
            M2, DINP, DM, DM, DM, DINP,
            0, (long)M2 * DINP, (long)DINP * DM, 0,
            nullptr, 0, 0);

        conv_kernel<<<(int)((2L * M2 * CONVD_ + 255) / 256), 256>>>(m_conv_w, m_conv_b, i);
        dt_kernel<<<(2 * M2 * HH + 255) / 256, 256>>>(m_dt, m_Alog, i);
        scan_kernel<<<dim3(HH, BB, 2), 256>>>(m_D, i);
        gnorm_kernel<<<dim3(M2, 2), 256>>>(m_norm_w, i);

        // out_proj, both directions fused along K=2048 (kh splits the weight)
        sgemm<64,64,4,4, 1,0,1><<<dim3(DM / 64, (M2 + 63) / 64, 1), 256>>>(
            y2, m_out_w + (long)(2 * i) * DM * DI_, nullptr, h,
            M2, DM, 2 * DI_, 2 * DI_, DI_, DM,
            0, 0, 0, 0, nullptr, DI_, (long)DM * DI_);
    }

    // 6. classifier: [2036,512] x [512,41] + bias -> d_out
    sgemm<64,64,4,4, 1,0,0><<<dim3(1, (M2 + 63) / 64, 1), 256>>>(
        h, out_w, out_b, out,
        M2, 41, DM, DM, DM, 41,
        0, 0, 0, 0, nullptr, 0, 0);
}

// round 5
// speedup vs baseline: 1.2594x; 1.1136x over previous
#include <cuda_runtime.h>
#include <cuda_bf16.h>
#include <math.h>
#include <stdint.h>

#define BB 4
#define TT 2048
#define DIN 513
#define TO 509
#define M2 (BB*TO)       /* 2036 */
#define DM 512
#define PROJD 4096
#define LL 5
#define DSTATE 64
#define DCONV 4
#define HD 64
#define DI_ 1024
#define HH 16
#define CONVD_ 1152      /* DI + 2*DSTATE */
#define DINP 2192        /* 2*DI + 2*DSTATE + H */
#define EPSF 1e-5f

#define K3P_IN  1536     /* 3*512  */
#define K3P_W2  12288    /* 3*4096 */
#define K3P_OUT 6144     /* 3*2048 */
#define K3P_W1  21568    /* 3*7182=21546 padded to 32-mult */

// -------------------- scratch (device globals; no runtime alloc) ------------
__device__ float g_h0[(size_t)BB*TT*DIN];
__device__ float g_h1[(size_t)M2*PROJD];
__device__ float g_h [(size_t)M2*DM];
__device__ float g_hn[(size_t)M2*DM];
__device__ float g_zx[(size_t)2*M2*DINP];
__device__ float g_xbc[(size_t)2*M2*CONVD_];
__device__ float g_dt[(size_t)2*M2*HH];
__device__ float g_dA[(size_t)2*M2*HH];
__device__ float g_y [(size_t)2*M2*DI_];
__device__ float g_y2[(size_t)M2*2*DI_];
__device__ __align__(16) __nv_bfloat16 g_a3[(size_t)BB*TO*K3P_W1];
__device__ __align__(16) __nv_bfloat16 g_w3[(size_t)PROJD*K3P_W1];

__device__ __forceinline__ uint32_t smem_u32(const void* p) {
    uint32_t a;
    asm("{ .reg .u64 t; cvta.to.shared.u64 t, %1; cvt.u32.u64 %0, t; }"
        : "=r"(a) : "l"(p));
    return a;
}

// ==================== mma.sync bf16 GEMM (legacy tensor path) ===============
// C[M,N] (+bias)(+act)(+=) = A3[M,K3]_bf16 @ W3[N,K3]_bf16^T   (K3 % 32 == 0)
// grid (ceil(N/BN), ceil(M/128), Z); per z: A+=sA, W+=sW, C+=sC. 256 threads.
#define SPITCH 40   /* bf16 elements per smem row (32 data + 8 pad) = 80 bytes */

template<int BN, int ACT, int ACCUM>
__global__ __launch_bounds__(256)
void mma_gemm(const __nv_bfloat16* __restrict__ A, const __nv_bfloat16* __restrict__ W,
              const float* __restrict__ bias, float* __restrict__ C,
              int M, int N, int K3, int ldc, long sA, long sW, long sC)
{
    constexpr int NN = BN / 16;   // n8-frag pairs per warp -> frags = NN
    constexpr int NB = BN / 32;   // ldmatrix.x4 count for B per k-step
    constexpr int LB = BN / 64;   // B staging uint4 per thread

    __shared__ __align__(16) __nv_bfloat16 As[128 * SPITCH];
    __shared__ __align__(16) __nv_bfloat16 Bs[BN  * SPITCH];

    int tid = threadIdx.x;
    int wid = tid >> 5, lane = tid & 31;
    int z = blockIdx.z;
    A += (long)z * sA;  W += (long)z * sW;  C += (long)z * sC;
    int row0 = blockIdx.y * 128, col0 = blockIdx.x * BN;
    int wm = wid & 3;          // 4 m-slices of 32
    int wn = wid >> 2;         // 2 n-slices of BN/2

    float acc[2][NN][4];
#pragma unroll
    for (int i = 0; i < 2; i++)
#pragma unroll
        for (int j = 0; j < NN; j++)
#pragma unroll
            for (int q = 0; q < 4; q++) acc[i][j][q] = 0.f;

    uint4 ra[2], rb[LB > 0 ? LB : 1];

    auto loadG = [&](int k0) {
#pragma unroll
        for (int l = 0; l < 2; l++) {
            int idx = tid + l * 256;
            int r = idx >> 2, c = idx & 3;
            int gr = row0 + r;
            uint4 v = make_uint4(0u, 0u, 0u, 0u);
            if (gr < M) v = *reinterpret_cast<const uint4*>(A + (long)gr * K3 + k0 + c * 8);
            ra[l] = v;
        }
#pragma unroll
        for (int l = 0; l < LB; l++) {
            int idx = tid + l * 256;
            int r = idx >> 2, c = idx & 3;
            int gn = col0 + r;
            uint4 v = make_uint4(0u, 0u, 0u, 0u);
            if (gn < N) v = *reinterpret_cast<const uint4*>(W + (long)gn * K3 + k0 + c * 8);
            rb[l] = v;
        }
    };
    auto storeS = [&]() {
#pragma unroll
        for (int l = 0; l < 2; l++) {
            int idx = tid + l * 256;
            int r = idx >> 2, c = idx & 3;
            *reinterpret_cast<uint4*>(As + r * SPITCH + c * 8) = ra[l];
        }
#pragma unroll
        for (int l = 0; l < LB; l++) {
            int idx = tid + l * 256;
            int r = idx >> 2, c = idx & 3;
            *reinterpret_cast<uint4*>(Bs + r * SPITCH + c * 8) = rb[l];
        }
    };

    // ldmatrix lane bases (bytes); row pitch = 80 bytes
    uint32_t a_base = smem_u32(As) + (uint32_t)((wm * 32 + (lane & 15)) * 80 + (lane >> 4) * 16);
    uint32_t b_base = smem_u32(Bs) + (uint32_t)((wn * (BN / 2) + ((lane >> 4) & 1) * 8 + (lane & 7)) * 80
                                                + ((lane >> 3) & 1) * 16);

    auto compute = [&]() {
#pragma unroll
        for (int ks = 0; ks < 2; ks++) {
            uint32_t a[2][4];
#pragma unroll
            for (int mm = 0; mm < 2; mm++) {
                uint32_t ad = a_base + (uint32_t)(mm * 16 * 80 + ks * 32);
                asm volatile("ldmatrix.sync.aligned.m8n8.x4.shared.b16 {%0,%1,%2,%3}, [%4];"
                    : "=r"(a[mm][0]), "=r"(a[mm][1]), "=r"(a[mm][2]), "=r"(a[mm][3])
                    : "r"(ad));
            }
            uint32_t b[NB][4];
#pragma unroll
            for (int nb = 0; nb < NB; nb++) {
                uint32_t bd = b_base + (uint32_t)(nb * 16 * 80 + ks * 32);
                asm volatile("ldmatrix.sync.aligned.m8n8.x4.shared.b16 {%0,%1,%2,%3}, [%4];"
                    : "=r"(b[nb][0]), "=r"(b[nb][1]), "=r"(b[nb][2]), "=r"(b[nb][3])
                    : "r"(bd));
            }
#pragma unroll
            for (int mm = 0; mm < 2; mm++)
#pragma unroll
                for (int nn = 0; nn < NN; nn++) {
                    uint32_t b0 = b[nn >> 1][(nn & 1) * 2];
                    uint32_t b1 = b[nn >> 1][(nn & 1) * 2 + 1];
                    asm volatile(
                        "mma.sync.aligned.m16n8k16.row.col.f32.bf16.bf16.f32 "
                        "{%0,%1,%2,%3}, {%4,%5,%6,%7}, {%8,%9}, {%0,%1,%2,%3};"
                        : "+f"(acc[mm][nn][0]), "+f"(acc[mm][nn][1]),
                          "+f"(acc[mm][nn][2]), "+f"(acc[mm][nn][3])
                        : "r"(a[mm][0]), "r"(a[mm][1]), "r"(a[mm][2]), "r"(a[mm][3]),
                          "r"(b0), "r"(b1));
                }
        }
    };

    loadG(0);
    storeS();
    __syncthreads();
    int NC = K3 >> 5;
    for (int ch = 1; ch < NC; ch++) {
        loadG(ch << 5);
        compute();
        __syncthreads();
        storeS();
        __syncthreads();
    }
    compute();

    // epilogue: d frag mapping (g = lane>>2 row, t = lane&3 col-pair)
    int g = lane >> 2, t = lane & 3;
#pragma unroll
    for (int mm = 0; mm < 2; mm++) {
#pragma unroll
        for (int half = 0; half < 2; half++) {
            int gr = row0 + wm * 32 + mm * 16 + g + half * 8;
            if (gr >= M) continue;
#pragma unroll
            for (int nn = 0; nn < NN; nn++) {
                int gn = col0 + wn * (BN / 2) + nn * 8 + t * 2;
                float v0 = acc[mm][nn][half * 2];
                float v1 = acc[mm][nn][half * 2 + 1];
#pragma unroll
                for (int e = 0; e < 2; e++) {
                    int gnn = gn + e;
                    if (gnn >= N) continue;
                    float v = e ? v1 : v0;
                    if (bias) v += bias[gnn];
                    if (ACT == 1) v = v / (1.f + fabsf(v));
                    long ci = (long)gr * ldc + gnn;
                    if (ACCUM) v += C[ci];
                    C[ci] = v;
                }
            }
        }
    }
}

// ---- fp32 -> 3-split bf16 conversions ---------------------------------------
__global__ void cvt_w3(const float* __restrict__ W, __nv_bfloat16* __restrict__ dst,
                       int N, int K, int ldw, int K3P, int kh, long swh) {
    int Kt = K3P / 3 + 1;
    long idx = (long)blockIdx.x * blockDim.x + threadIdx.x;
    if (idx >= (long)N * Kt) return;
    int n = (int)(idx / Kt), k = (int)(idx % Kt);
    float v = 0.f;
    if (k < K) {
        const float* Wp = W;
        int kk = k;
        if (kh && kk >= kh) { Wp += swh; kk -= kh; }
        v = Wp[(long)n * ldw + kk];
    }
    __nv_bfloat16 hi = __float2bfloat16(v);
    __nv_bfloat16 lo = __float2bfloat16(v - __bfloat162float(hi));
    long base = (long)n * K3P + 3L * k;
    if (3L * k     < K3P) dst[base]     = hi;
    if (3L * k + 1 < K3P) dst[base + 1] = hi;
    if (3L * k + 2 < K3P) dst[base + 2] = lo;
}
__global__ void cvt_a3(const float* __restrict__ A, __nv_bfloat16* __restrict__ dst,
                       int Mr, int K, int lda, int K3P, long szA, long szD) {
    int z = blockIdx.z;
    A += (long)z * szA; dst += (long)z * szD;
    int Kt = K3P / 3 + 1;
    long idx = (long)blockIdx.x * blockDim.x + threadIdx.x;
    if (idx >= (long)Mr * Kt) return;
    int r = (int)(idx / Kt), k = (int)(idx % Kt);
    float v = (k < K) ? A[(long)r * lda + k] : 0.f;
    __nv_bfloat16 hi = __float2bfloat16(v);
    __nv_bfloat16 lo = __float2bfloat16(v - __bfloat162float(hi));
    long base = (long)r * K3P + 3L * k;
    if (3L * k     < K3P) dst[base]     = hi;
    if (3L * k + 1 < K3P) dst[base + 1] = lo;
    if (3L * k + 2 < K3P) dst[base + 2] = hi;
}

// ==================== f32x2 SIMT GEMM (day + classifier) ====================
__device__ __forceinline__ unsigned long long pack_dup(float a) {
    unsigned long long r;
    unsigned int au = __float_as_uint(a);
    asm("mov.b64 %0, {%1, %1};" : "=l"(r) : "r"(au));
    return r;
}
__device__ __forceinline__ void fma_x2(unsigned long long& acc,
                                       unsigned long long a, unsigned long long b) {
    asm("fma.rn.f32x2 %0, %1, %2, %0;" : "+l"(acc) : "l"(a), "l"(b));
}
__device__ __forceinline__ void unpack_x2(unsigned long long v, float& lo, float& hi) {
    unsigned int ul, uh;
    asm("mov.b64 {%0, %1}, %2;" : "=r"(ul), "=r"(uh) : "l"(v));
    lo = __uint_as_float(ul); hi = __uint_as_float(uh);
}

template<int BM, int BN, int TM, int TN, int TB, int ACT, int ACCUM>
__global__ __launch_bounds__((BM/TM)*(BN/TN))
void sgemm(const float* __restrict__ A, const float* __restrict__ W,
           const float* __restrict__ bias, float* __restrict__ C,
           int M, int N, int K, int lda, int ldw, int ldc,
           long sA, long sC, long sW, long sB,
           const int* __restrict__ widx)
{
    constexpr int NT = (BM/TM)*(BN/TN);
    constexpr int LA = BM*8/NT;
    constexpr int LB = BN*8/NT;
    constexpr int NX = BN/TN;

    int bz = blockIdx.z;
    A += (long)bz * sA;
    C += (long)bz * sC;
    {
        int wi = widx ? widx[bz] : bz;
        W += (long)wi * sW;
        if (bias) bias += (long)wi * sB;
    }

    __shared__ __align__(16) float As[8][BM];
    __shared__ __align__(16) float Bs[8][BN];

    int tid = threadIdx.x;
    int tx = tid % NX, ty = tid / NX;
    int row0 = blockIdx.y * BM, col0 = blockIdx.x * BN;

    unsigned long long acc[TM][TN/2];
#pragma unroll
    for (int i = 0; i < TM; i++)
#pragma unroll
        for (int j = 0; j < TN/2; j++) acc[i][j] = 0ull;

    float ra[LA], rb[LB];
    auto loadG = [&](int k0) {
#pragma unroll
        for (int l = 0; l < LA; l++) {
            int i = tid + l * NT;
            int r = i >> 3, c = i & 7;
            int gr = row0 + r, gk = k0 + c;
            ra[l] = (gr < M && gk < K) ? A[(long)gr * lda + gk] : 0.f;
        }
#pragma unroll
        for (int l = 0; l < LB; l++) {
            int i = tid + l * NT;
            int r, c;
            if (TB) { r = i >> 3; c = i & 7; }
            else    { r = i & (BN - 1); c = i / BN; }
            int gn = col0 + r, gk = k0 + c;
            float v = 0.f;
            if (gn < N && gk < K)
                v = TB ? W[(long)gn * ldw + gk] : W[(long)gk * ldw + gn];
            rb[l] = v;
        }
    };
    auto storeS = [&]() {
#pragma unroll
        for (int l = 0; l < LA; l++) {
            int i = tid + l * NT;
            As[i & 7][i >> 3] = ra[l];
        }
#pragma unroll
        for (int l = 0; l < LB; l++) {
            int i = tid + l * NT;
            if (TB) Bs[i & 7][i >> 3] = rb[l];
            else    Bs[i / BN][i & (BN - 1)] = rb[l];
        }
    };
    auto compute = [&]() {
#pragma unroll
        for (int kk = 0; kk < 8; kk++) {
            float a[TM];
            const float4* ap4 = reinterpret_cast<const float4*>(&As[kk][ty * TM]);
#pragma unroll
            for (int q = 0; q < TM/4; q++) {
                float4 tt = ap4[q];
                a[4*q+0] = tt.x; a[4*q+1] = tt.y; a[4*q+2] = tt.z; a[4*q+3] = tt.w;
            }
            unsigned long long bp[TN/2];
            const ulonglong2* bp2 = reinterpret_cast<const ulonglong2*>(&Bs[kk][tx * TN]);
#pragma unroll
            for (int q = 0; q < TN/4; q++) {
                ulonglong2 tt = bp2[q];
                bp[2*q] = tt.x; bp[2*q+1] = tt.y;
            }
#pragma unroll
            for (int i = 0; i < TM; i++) {
                unsigned long long ap = pack_dup(a[i]);
#pragma unroll
                for (int j = 0; j < TN/2; j++) fma_x2(acc[i][j], ap, bp[j]);
            }
        }
    };

    loadG(0);
    storeS();
    __syncthreads();
    for (int k0 = 8; k0 < K; k0 += 8) {
        loadG(k0);
        compute();
        __syncthreads();
        storeS();
        __syncthreads();
    }
    compute();

#pragma unroll
    for (int i = 0; i < TM; i++) {
        int gr = row0 + ty * TM + i;
        if (gr >= M) continue;
#pragma unroll
        for (int j = 0; j < TN/2; j++) {
            float v0, v1;
            unpack_x2(acc[i][j], v0, v1);
            int gn0 = col0 + tx * TN + 2*j;
#pragma unroll
            for (int e = 0; e < 2; e++) {
                int gn = gn0 + e;
                if (gn >= N) continue;
                float v = e ? v1 : v0;
                if (bias) v += bias[gn];
                if (ACT == 1) v = v / (1.f + fabsf(v));
                long ci = (long)gr * ldc + gn;
                if (ACCUM) v += C[ci];
                C[ci] = v;
            }
        }
    }
}

// -------------------- pointwise kernels -------------------------------------
__global__ void copy_xt(const float* __restrict__ x) {
    int i = blockIdx.x * blockDim.x + threadIdx.x;
    if (i < BB * TT) g_h0[(long)i * DIN + (DIN - 1)] = x[(long)i * DIN + (DIN - 1)];
}

__global__ void ln_kernel(const float* __restrict__ w, const float* __restrict__ b) {
    int row = blockIdx.x;
    const float* xr = g_h + (long)row * DM;
    float* orow = g_hn + (long)row * DM;
    int tid = threadIdx.x;
    float v[4], s = 0.f, s2 = 0.f;
#pragma unroll
    for (int i = 0; i < 4; i++) { v[i] = xr[tid + i * 128]; s += v[i]; s2 += v[i] * v[i]; }
#pragma unroll
    for (int o = 16; o > 0; o >>= 1) {
        s  += __shfl_down_sync(0xffffffffu, s, o);
        s2 += __shfl_down_sync(0xffffffffu, s2, o);
    }
    __shared__ float sh[8];
    int wid = tid >> 5, lane = tid & 31;
    if (!lane) { sh[wid] = s; sh[4 + wid] = s2; }
    __syncthreads();
    if (tid == 0) {
        float ts = 0.f, t2 = 0.f;
        for (int i = 0; i < 4; i++) { ts += sh[i]; t2 += sh[4 + i]; }
        sh[0] = ts; sh[4] = t2;
    }
    __syncthreads();
    float mu = sh[0] / (float)DM;
    float var = sh[4] / (float)DM - mu * mu;
    float inv = rsqrtf(var + EPSF);
#pragma unroll
    for (int i = 0; i < 4; i++) {
        int c = tid + i * 128;
        orow[c] = (v[i] - mu) * inv * w[c] + b[c];
    }
}

__global__ void conv_kernel(const float* __restrict__ conv_w,
                            const float* __restrict__ conv_b, int layer) {
    long idx = (long)blockIdx.x * blockDim.x + threadIdx.x;
    if (idx >= 2L * M2 * CONVD_) return;
    int c = (int)(idx % CONVD_);
    long r = idx / CONVD_;
    int dir = (int)(r / M2);
    int bt = (int)(r % M2);
    int b = bt / TO, t = bt % TO;
    int m = 2 * layer + dir;
    const float* wc = conv_w + ((long)m * CONVD_ + c) * DCONV;
    const float* zbase = g_zx + (long)dir * M2 * DINP + (long)b * TO * DINP;
    float s = conv_b[(long)m * CONVD_ + c];
#pragma unroll
    for (int j = 0; j < DCONV; j++) {
        int tt = dir ? (t + 3 - j) : (t - 3 + j);
        if (tt >= 0 && tt < TO) s += wc[j] * zbase[(long)tt * DINP + DI_ + c];
    }
    s = s / (1.f + expf(-s));
    g_xbc[(long)dir * M2 * CONVD_ + (long)bt * CONVD_ + c] = s;
}

__device__ __forceinline__ float softplusf(float x) {
    return x > 0.f ? x + log1pf(expf(-x)) : log1pf(expf(x));
}

__global__ void dt_kernel(const float* __restrict__ dtb,
                          const float* __restrict__ alog, int layer) {
    int idx = blockIdx.x * blockDim.x + threadIdx.x;
    if (idx >= 2 * M2 * HH) return;
    int h = idx % HH;
    int r = idx / HH;
    int dir = r / M2, bt = r % M2;
    int m = 2 * layer + dir;
    float raw = g_zx[((long)dir * M2 + bt) * DINP + DI_ + CONVD_ + h] + dtb[m * HH + h];
    float dt = softplusf(raw);
    float A = -expf(alog[m * HH + h]);
    g_dt[idx] = dt;
    g_dA[idx] = expf(dt * A);
}

__global__ void scan_kernel(const float* __restrict__ Dp, int layer) {
    int h = blockIdx.x, b = blockIdx.y, dir = blockIdx.z;
    int m = 2 * layer + dir;
    int tid = threadIdx.x;
    int p = tid & 63, g = tid >> 6;
    float Dh = Dp[m * HH + h];

    __shared__ float sx[64], sB[64], sC[64], yr[256];
    __shared__ float sda, sdt;

    float st[16];
#pragma unroll
    for (int i = 0; i < 16; i++) st[i] = 0.f;

    const float* xbase  = g_xbc + (long)dir * M2 * CONVD_ + (long)b * TO * CONVD_;
    float*       ybase  = g_y   + (long)dir * M2 * DI_    + (long)b * TO * DI_;
    const float* dabase = g_dA  + ((long)dir * M2 + (long)b * TO) * HH;
    const float* dtbase = g_dt  + ((long)dir * M2 + (long)b * TO) * HH;

    for (int s_ = 0; s_ < TO; s_++) {
        int t = dir ? (TO - 1 - s_) : s_;
        const float* xr = xbase + (long)t * CONVD_;
        if (tid < 64)       sx[tid]       = xr[h * 64 + tid];
        else if (tid < 128) sB[tid - 64]  = xr[DI_ + (tid - 64)];
        else if (tid < 192) sC[tid - 128] = xr[DI_ + DSTATE + (tid - 128)];
        else if (tid == 192) sda = dabase[(long)t * HH + h];
        else if (tid == 193) sdt = dtbase[(long)t * HH + h];
        __syncthreads();

        float dtx = sdt * sx[p];
        float da = sda;
        float yp = 0.f;
#pragma unroll
        for (int i = 0; i < 16; i++) {
            int n = g * 16 + i;
            st[i] = st[i] * da + dtx * sB[n];
            yp += st[i] * sC[n];
        }
        yr[tid] = yp;
        __syncthreads();
        if (g == 0) {
            float y = yr[p] + yr[64 + p] + yr[128 + p] + yr[192 + p] + Dh * sx[p];
            ybase[(long)t * DI_ + h * 64 + p] = y;
        }
        __syncthreads();
    }
}

__global__ void gnorm_kernel(const float* __restrict__ norm_w, int layer) {
    int row = blockIdx.x, dir = blockIdx.y;
    int m = 2 * layer + dir;
    const float* yrow = g_y + ((long)dir * M2 + row) * DI_;
    const float* zrow = g_zx + ((long)dir * M2 + row) * DINP;
    float* orow = g_y2 + (long)row * (2 * DI_) + (long)dir * DI_;
    int tid = threadIdx.x;
    float v[4], ss = 0.f;
#pragma unroll
    for (int i = 0; i < 4; i++) {
        int c = tid + i * 256;
        float z = zrow[c];
        float val = yrow[c] * (z / (1.f + expf(-z)));
        v[i] = val;
        ss += val * val;
    }
#pragma unroll
    for (int o = 16; o > 0; o >>= 1) ss += __shfl_down_sync(0xffffffffu, ss, o);
    __shared__ float sh[8];
    int wid = tid >> 5, lane = tid & 31;
    if (!lane) sh[wid] = ss;
    __syncthreads();
    if (tid == 0) { float tot = 0.f; for (int i = 0; i < 8; i++) tot += sh[i]; sh[0] = tot; }
    __syncthreads();
    float inv = rsqrtf(sh[0] / (float)DI_ + EPSF);
#pragma unroll
    for (int i = 0; i < 4; i++) {
        int c = tid + i * 256;
        orow[c] = v[i] * inv * norm_w[(long)m * DI_ + c];
    }
}

// -------------------- host orchestration ------------------------------------
static inline int cvt_grid(long n) { return (int)((n + 255) / 256); }

extern "C" void kernel_launch(void* const* d_in, const int* in_sizes, int n_in,
                              void* d_out, int out_size) {
    const float* x        = (const float*)d_in[0];
    const int*   day_idx  = (const int*)  d_in[1];
    const float* day_w    = (const float*)d_in[2];
    const float* day_b    = (const float*)d_in[3];
    const float* w1       = (const float*)d_in[4];
    const float* b1       = (const float*)d_in[5];
    const float* w2       = (const float*)d_in[6];
    const float* b2       = (const float*)d_in[7];
    const float* ln_w     = (const float*)d_in[8];
    const float* ln_b     = (const float*)d_in[9];
    const float* m_in_w   = (const float*)d_in[10];
    const float* m_conv_w = (const float*)d_in[11];
    const float* m_conv_b = (const float*)d_in[12];
    const float* m_dt     = (const float*)d_in[13];
    const float* m_Alog   = (const float*)d_in[14];
    const float* m_D      = (const float*)d_in[15];
    const float* m_norm_w = (const float*)d_in[16];
    const float* m_out_w  = (const float*)d_in[17];
    const float* out_w    = (const float*)d_in[18];
    const float* out_b    = (const float*)d_in[19];
    float* out = (float*)d_out;

    float *h0, *h1, *h, *hn, *zx, *y2;
    __nv_bfloat16 *a3, *w3;
    cudaGetSymbolAddress((void**)&h0, g_h0);
    cudaGetSymbolAddress((void**)&h1, g_h1);
    cudaGetSymbolAddress((void**)&h,  g_h);
    cudaGetSymbolAddress((void**)&hn, g_hn);
    cudaGetSymbolAddress((void**)&zx, g_zx);
    cudaGetSymbolAddress((void**)&y2, g_y2);
    cudaGetSymbolAddress((void**)&a3, g_a3);
    cudaGetSymbolAddress((void**)&w3, g_w3);

    // 1. day transform (f32x2 SIMT; per-batch weight) -> g_h0[:, :, :512]
    sgemm<128,128,8,8, 0,1,0><<<dim3(4, 16, BB), 256>>>(
        x, day_w, day_b, h0,
        TT, 512, 512, DIN, 512, DIN,
        (long)TT * DIN, (long)TT * DIN, 512L * 512L, 512L, day_idx);

    // 2. passthrough last channel
    copy_xt<<<(BB * TT + 255) / 256, 256>>>(x);

    // 3. w1 patch projection via mma
    {
        int Kt1 = K3P_W1 / 3 + 1;
        cvt_w3<<<cvt_grid((long)PROJD * Kt1), 256>>>(w1, w3, PROJD, 7182, 7182, K3P_W1, 0, 0);
        cvt_a3<<<dim3(cvt_grid((long)TO * Kt1), 1, BB), 256>>>(
            h0, a3, TO, 7182, 4 * DIN, K3P_W1, (long)TT * DIN, (long)TO * K3P_W1);
        mma_gemm<128,1,0><<<dim3(PROJD / 128, 4, BB), 256>>>(
            a3, w3, b1, h1, TO, PROJD, K3P_W1, PROJD,
            (long)TO * K3P_W1, 0, (long)TO * PROJD);
    }

    // 4. w2 via mma (BN=64 for occupancy: 8x16=128 CTAs)
    {
        int Kt = K3P_W2 / 3 + 1;
        cvt_w3<<<cvt_grid((long)DM * Kt), 256>>>(w2, w3, DM, PROJD, PROJD, K3P_W2, 0, 0);
        cvt_a3<<<dim3(cvt_grid((long)M2 * Kt), 1, 1), 256>>>(
            h1, a3, M2, PROJD, PROJD, K3P_W2, 0, 0);
        mma_gemm<64,0,0><<<dim3(DM / 64, 16, 1), 256>>>(
            a3, w3, b2, h, M2, DM, K3P_W2, DM, 0, 0, 0);
    }

    // 5. layers
    for (int i = 0; i < LL; i++) {
        ln_kernel<<<M2, 128>>>(ln_w + (long)i * DM, ln_b + (long)i * DM);

        // in_proj: both directions (z=2), mma
        {
            int Kt = K3P_IN / 3 + 1;
            cvt_w3<<<cvt_grid((long)(2 * DINP) * Kt), 256>>>(
                m_in_w + (long)(2 * i) * DINP * DM, w3, 2 * DINP, DM, DM, K3P_IN, 0, 0);
            cvt_a3<<<dim3(cvt_grid((long)M2 * Kt), 1, 1), 256>>>(
                hn, a3, M2, DM, DM, K3P_IN, 0, 0);
            mma_gemm<128,0,0><<<dim3((DINP + 127) / 128, 16, 2), 256>>>(
                a3, w3, nullptr, zx, M2, DINP, K3P_IN, DINP,
                0, (long)DINP * K3P_IN, (long)M2 * DINP);
        }

        conv_kernel<<<(int)((2L * M2 * CONVD_ + 255) / 256), 256>>>(m_conv_w, m_conv_b, i);
        dt_kernel<<<(2 * M2 * HH + 255) / 256, 256>>>(m_dt, m_Alog, i);
        scan_kernel<<<dim3(HH, BB, 2), 256>>>(m_D, i);
        gnorm_kernel<<<dim3(M2, 2), 256>>>(m_norm_w, i);

        // out_proj: dirs fused along K (kh split), accumulate into h
        {
            int Kt = K3P_OUT / 3 + 1;
            cvt_w3<<<cvt_grid((long)DM * Kt), 256>>>(
                m_out_w + (long)(2 * i) * DM * DI_, w3, DM, 2 * DI_, DI_, K3P_OUT,
                DI_, (long)DM * DI_);
            cvt_a3<<<dim3(cvt_grid((long)M2 * Kt), 1, 1), 256>>>(
                y2, a3, M2, 2 * DI_, 2 * DI_, K3P_OUT, 0, 0);
            mma_gemm<64,0,1><<<dim3(DM / 64, 16, 1), 256>>>(
                a3, w3, nullptr, h, M2, DM, K3P_OUT, DM, 0, 0, 0);
        }
    }

    // 6. classifier (small; f32x2 SIMT)
    sgemm<64,64,4,4, 1,0,0><<<dim3(1, (M2 + 63) / 64, 1), 256>>>(
        h, out_w, out_b, out,
        M2, 41, DM, DM, DM, 41,
        0, 0, 0, 0, nullptr);
}

// round 7
// speedup vs baseline: 2.5987x; 2.0634x over previous
#include <cuda_runtime.h>
#include <cuda_bf16.h>
#include <math.h>
#include <stdint.h>

#define BB 4
#define TT 2048
#define DIN 513
#define TO 509
#define M2 (BB*TO)       /* 2036 */
#define DM 512
#define PROJD 4096
#define LL 5
#define DSTATE 64
#define DCONV 4
#define DI_ 1024
#define HH 16
#define CONVD_ 1152      /* DI + 2*DSTATE */
#define DINP 2192        /* 2*DI + 2*DSTATE + H */
#define EPSF 1e-5f

#define K3P_IN  1536     /* 3*512  */
#define K3P_W2  12288    /* 3*4096 */
#define K3P_OUT 6144     /* 3*2048 */
#define K3P_W1  21568    /* 3*7182=21546 padded to 32-mult */

// -------------------- scratch (device globals; no runtime alloc) ------------
__device__ float g_h0[(size_t)BB*TT*DIN];
__device__ float g_h1[(size_t)M2*PROJD];
__device__ float g_h [(size_t)M2*DM];
__device__ float g_hn[(size_t)M2*DM];
__device__ float g_zx[(size_t)2*M2*DINP];
__device__ float g_xbc[(size_t)2*M2*CONVD_];
__device__ float g_y [(size_t)2*M2*DI_];
__device__ float g_y2[(size_t)M2*2*DI_];
__device__ __align__(16) __nv_bfloat16 g_a3[(size_t)BB*TO*K3P_W1];
__device__ __align__(16) __nv_bfloat16 g_w3[(size_t)PROJD*K3P_W1];

__device__ __forceinline__ uint32_t smem_u32(const void* p) {
    uint32_t a;
    asm("{ .reg .u64 t; cvta.to.shared.u64 t, %1; cvt.u32.u64 %0, t; }"
        : "=r"(a) : "l"(p));
    return a;
}

// ==================== mma.sync bf16 GEMM, 3-stage cp.async pipeline =========
// C[M,N] (+bias)(+act)(+=) = A3[M,K3]_bf16 @ W3[N,K3]_bf16^T   (K3 % 32 == 0)
// grid (ceil(N/BN), ceil(M/128), Z); per z: A+=sA, W+=sW, C+=sC. 256 threads.
#define SPITCH 40   /* bf16 per smem row (32 data + 8 pad) = 80 bytes */
#define STAGES 3

template<int BN, int ACT, int ACCUM>
__global__ __launch_bounds__(256)
void mma_gemm(const __nv_bfloat16* __restrict__ A, const __nv_bfloat16* __restrict__ W,
              const float* __restrict__ bias, float* __restrict__ C,
              int M, int N, int K3, int ldc, long sA, long sW, long sC)
{
    constexpr int NN = BN / 16;
    constexpr int NB = BN / 32;
    constexpr int LB = BN / 64;
    constexpr int ABYTES = 128 * SPITCH * 2;   // per stage
    constexpr int BBYTES = BN  * SPITCH * 2;

    extern __shared__ __align__(16) char dsm[];
    uint32_t asb = smem_u32(dsm);
    uint32_t bsb = asb + STAGES * ABYTES;

    int tid = threadIdx.x;
    int wid = tid >> 5, lane = tid & 31;
    int z = blockIdx.z;
    A += (long)z * sA;  W += (long)z * sW;  C += (long)z * sC;
    int row0 = blockIdx.y * 128, col0 = blockIdx.x * BN;
    int wm = wid & 3, wn = wid >> 2;

    float acc[2][NN][4];
#pragma unroll
    for (int i = 0; i < 2; i++)
#pragma unroll
        for (int j = 0; j < NN; j++)
#pragma unroll
            for (int q = 0; q < 4; q++) acc[i][j][q] = 0.f;

    auto loadStage = [&](int ch, int s) {
        int k0 = ch << 5;
        uint32_t sa = asb + s * ABYTES;
#pragma unroll
        for (int l = 0; l < 2; l++) {
            int idx = tid + l * 256;
            int r = idx >> 2, c = idx & 3;
            int gr = row0 + r;
            int grc = gr < M ? gr : M - 1;
            const __nv_bfloat16* src = A + (long)grc * K3 + k0 + c * 8;
            uint32_t dst = sa + (uint32_t)(r * (SPITCH * 2) + c * 16);
            int bytes = (gr < M) ? 16 : 0;
            asm volatile("cp.async.cg.shared.global [%0], [%1], 16, %2;"
                :: "r"(dst), "l"(src), "r"(bytes));
        }
        uint32_t sb2 = bsb + s * BBYTES;
#pragma unroll
        for (int l = 0; l < LB; l++) {
            int idx = tid + l * 256;
            int r = idx >> 2, c = idx & 3;
            int gn = col0 + r;
            int gnc = gn < N ? gn : N - 1;
            const __nv_bfloat16* src = W + (long)gnc * K3 + k0 + c * 8;
            uint32_t dst = sb2 + (uint32_t)(r * (SPITCH * 2) + c * 16);
            int bytes = (gn < N) ? 16 : 0;
            asm volatile("cp.async.cg.shared.global [%0], [%1], 16, %2;"
                :: "r"(dst), "l"(src), "r"(bytes));
        }
        asm volatile("cp.async.commit_group;" ::: "memory");
    };

    auto compute = [&](int s) {
        uint32_t a_base = asb + s * ABYTES
            + (uint32_t)((wm * 32 + (lane & 15)) * 80 + (lane >> 4) * 16);
        uint32_t b_base = bsb + s * BBYTES
            + (uint32_t)((wn * (BN / 2) + ((lane >> 4) & 1) * 8 + (lane & 7)) * 80
                         + ((lane >> 3) & 1) * 16);
#pragma unroll
        for (int ks = 0; ks < 2; ks++) {
            uint32_t a[2][4];
#pragma unroll
            for (int mm = 0; mm < 2; mm++) {
                uint32_t ad = a_base + (uint32_t)(mm * 16 * 80 + ks * 32);
                asm volatile("ldmatrix.sync.aligned.m8n8.x4.shared.b16 {%0,%1,%2,%3}, [%4];"
                    : "=r"(a[mm][0]), "=r"(a[mm][1]), "=r"(a[mm][2]), "=r"(a[mm][3])
                    : "r"(ad));
            }
            uint32_t b[NB][4];
#pragma unroll
            for (int nb = 0; nb < NB; nb++) {
                uint32_t bd = b_base + (uint32_t)(nb * 16 * 80 + ks * 32);
                asm volatile("ldmatrix.sync.aligned.m8n8.x4.shared.b16 {%0,%1,%2,%3}, [%4];"
                    : "=r"(b[nb][0]), "=r"(b[nb][1]), "=r"(b[nb][2]), "=r"(b[nb][3])
                    : "r"(bd));
            }
#pragma unroll
            for (int mm = 0; mm < 2; mm++)
#pragma unroll
                for (int nn = 0; nn < NN; nn++) {
                    uint32_t b0 = b[nn >> 1][(nn & 1) * 2];
                    uint32_t b1 = b[nn >> 1][(nn & 1) * 2 + 1];
                    asm volatile(
                        "mma.sync.aligned.m16n8k16.row.col.f32.bf16.bf16.f32 "
                        "{%0,%1,%2,%3}, {%4,%5,%6,%7}, {%8,%9}, {%0,%1,%2,%3};"
                        : "+f"(acc[mm][nn][0]), "+f"(acc[mm][nn][1]),
                          "+f"(acc[mm][nn][2]), "+f"(acc[mm][nn][3])
                        : "r"(a[mm][0]), "r"(a[mm][1]), "r"(a[mm][2]), "r"(a[mm][3]),
                          "r"(b0), "r"(b1));
                }
        }
    };

    int NC = K3 >> 5;
    loadStage(0, 0);
    loadStage(1, 1);
    for (int ch = 0; ch < NC; ch++) {
        asm volatile("cp.async.wait_group 1;" ::: "memory");
        __syncthreads();
        compute(ch % 3);
        int nx = ch + 2;
        if (nx < NC) loadStage(nx, nx % 3);
    }

    int g = lane >> 2, t = lane & 3;
#pragma unroll
    for (int mm = 0; mm < 2; mm++) {
#pragma unroll
        for (int half = 0; half < 2; half++) {
            int gr = row0 + wm * 32 + mm * 16 + g + half * 8;
            if (gr >= M) continue;
#pragma unroll
            for (int nn = 0; nn < NN; nn++) {
                int gn = col0 + wn * (BN / 2) + nn * 8 + t * 2;
                float v0 = acc[mm][nn][half * 2];
                float v1 = acc[mm][nn][half * 2 + 1];
#pragma unroll
                for (int e = 0; e < 2; e++) {
                    int gnn = gn + e;
                    if (gnn >= N) continue;
                    float v = e ? v1 : v0;
                    if (bias) v += bias[gnn];
                    if (ACT == 1) v = v / (1.f + fabsf(v));
                    long ci = (long)gr * ldc + gnn;
                    if (ACCUM) v += C[ci];
                    C[ci] = v;
                }
            }
        }
    }
}

// ---- fp32 -> 3-split bf16 conversions (2D grid, no div) ---------------------
// weights: [hi,hi,lo]
__global__ void cvt_w3(const float* __restrict__ W, __nv_bfloat16* __restrict__ dst,
                       int K, int ldw, int K3P, int kh, long swh) {
    int n = blockIdx.y;
    int k = blockIdx.x * blockDim.x + threadIdx.x;
    int Kt = (K3P + 2) / 3;
    if (k >= Kt) return;
    float v = 0.f;
    if (k < K) {
        const float* Wp = W;
        int kk = k;
        if (kh && kk >= kh) { Wp += swh; kk -= kh; }
        v = Wp[(long)n * ldw + kk];
    }
    __nv_bfloat16 hi = __float2bfloat16(v);
    __nv_bfloat16 lo = __float2bfloat16(v - __bfloat162float(hi));
    long base = (long)n * K3P + 3L * k;
    dst[base] = hi;
    if (3L * k + 1 < K3P) dst[base + 1] = hi;
    if (3L * k + 2 < K3P) dst[base + 2] = lo;
}
// activations: [hi,lo,hi]
__global__ void cvt_a3(const float* __restrict__ A, __nv_bfloat16* __restrict__ dst,
                       int K, int lda, int K3P, long szA, long szD) {
    int z = blockIdx.z;
    A += (long)z * szA; dst += (long)z * szD;
    int r = blockIdx.y;
    int k = blockIdx.x * blockDim.x + threadIdx.x;
    int Kt = (K3P + 2) / 3;
    if (k >= Kt) return;
    float v = (k < K) ? A[(long)r * lda + k] : 0.f;
    __nv_bfloat16 hi = __float2bfloat16(v);
    __nv_bfloat16 lo = __float2bfloat16(v - __bfloat162float(hi));
    long base = (long)r * K3P + 3L * k;
    dst[base] = hi;
    if (3L * k + 1 < K3P) dst[base + 1] = lo;
    if (3L * k + 2 < K3P) dst[base + 2] = hi;
}

// ==================== f32x2 SIMT GEMM (day + classifier, exact fp32) ========
__device__ __forceinline__ unsigned long long pack_dup(float a) {
    unsigned long long r;
    unsigned int au = __float_as_uint(a);
    asm("mov.b64 %0, {%1, %1};" : "=l"(r) : "r"(au));
    return r;
}
__device__ __forceinline__ void fma_x2(unsigned long long& acc,
                                       unsigned long long a, unsigned long long b) {
    asm("fma.rn.f32x2 %0, %1, %2, %0;" : "+l"(acc) : "l"(a), "l"(b));
}
__device__ __forceinline__ void unpack_x2(unsigned long long v, float& lo, float& hi) {
    unsigned int ul, uh;
    asm("mov.b64 {%0, %1}, %2;" : "=r"(ul), "=r"(uh) : "l"(v));
    lo = __uint_as_float(ul); hi = __uint_as_float(uh);
}

template<int BM, int BN, int TM, int TN, int TB, int ACT>
__global__ __launch_bounds__((BM/TM)*(BN/TN))
void sgemm(const float* __restrict__ A, const float* __restrict__ W,
           const float* __restrict__ bias, float* __restrict__ C,
           int M, int N, int K, int lda, int ldw, int ldc,
           long sA, long sC, long sW, long sB,
           const int* __restrict__ widx)
{
    constexpr int NT = (BM/TM)*(BN/TN);
    constexpr int LA = BM*8/NT;
    constexpr int LB = BN*8/NT;
    constexpr int NX = BN/TN;

    int bz = blockIdx.z;
    A += (long)bz * sA;
    C += (long)bz * sC;
    {
        int wi = widx ? widx[bz] : bz;
        W += (long)wi * sW;
        if (bias) bias += (long)wi * sB;
    }

    __shared__ __align__(16) float As[8][BM];
    __shared__ __align__(16) float Bs[8][BN];

    int tid = threadIdx.x;
    int tx = tid % NX, ty = tid / NX;
    int row0 = blockIdx.y * BM, col0 = blockIdx.x * BN;

    unsigned long long acc[TM][TN/2];
#pragma unroll
    for (int i = 0; i < TM; i++)
#pragma unroll
        for (int j = 0; j < TN/2; j++) acc[i][j] = 0ull;

    float ra[LA], rb[LB];
    auto loadG = [&](int k0) {
#pragma unroll
        for (int l = 0; l < LA; l++) {
            int i = tid + l * NT;
            int r = i >> 3, c = i & 7;
            int gr = row0 + r, gk = k0 + c;
            ra[l] = (gr < M && gk < K) ? A[(long)gr * lda + gk] : 0.f;
        }
#pragma unroll
        for (int l = 0; l < LB; l++) {
            int i = tid + l * NT;
            int r, c;
            if (TB) { r = i >> 3; c = i & 7; }
            else    { r = i & (BN - 1); c = i / BN; }
            int gn = col0 + r, gk = k0 + c;
            float v = 0.f;
            if (gn < N && gk < K)
                v = TB ? W[(long)gn * ldw + gk] : W[(long)gk * ldw + gn];
            rb[l] = v;
        }
    };
    auto storeS = [&]() {
#pragma unroll
        for (int l = 0; l < LA; l++) {
            int i = tid + l * NT;
            As[i & 7][i >> 3] = ra[l];
        }
#pragma unroll
        for (int l = 0; l < LB; l++) {
            int i = tid + l * NT;
            if (TB) Bs[i & 7][i >> 3] = rb[l];
            else    Bs[i / BN][i & (BN - 1)] = rb[l];
        }
    };
    auto compute = [&]() {
#pragma unroll
        for (int kk = 0; kk < 8; kk++) {
            float a[TM];
            const float4* ap4 = reinterpret_cast<const float4*>(&As[kk][ty * TM]);
#pragma unroll
            for (int q = 0; q < TM/4; q++) {
                float4 tt = ap4[q];
                a[4*q+0] = tt.x; a[4*q+1] = tt.y; a[4*q+2] = tt.z; a[4*q+3] = tt.w;
            }
            unsigned long long bp[TN/2];
            const ulonglong2* bp2 = reinterpret_cast<const ulonglong2*>(&Bs[kk][tx * TN]);
#pragma unroll
            for (int q = 0; q < TN/4; q++) {
                ulonglong2 tt = bp2[q];
                bp[2*q] = tt.x; bp[2*q+1] = tt.y;
            }
#pragma unroll
            for (int i = 0; i < TM; i++) {
                unsigned long long ap = pack_dup(a[i]);
#pragma unroll
                for (int j = 0; j < TN/2; j++) fma_x2(acc[i][j], ap, bp[j]);
            }
        }
    };

    loadG(0);
    storeS();
    __syncthreads();
    for (int k0 = 8; k0 < K; k0 += 8) {
        loadG(k0);
        compute();
        __syncthreads();
        storeS();
        __syncthreads();
    }
    compute();

#pragma unroll
    for (int i = 0; i < TM; i++) {
        int gr = row0 + ty * TM + i;
        if (gr >= M) continue;
#pragma unroll
        for (int j = 0; j < TN/2; j++) {
            float v0, v1;
            unpack_x2(acc[i][j], v0, v1);
            int gn0 = col0 + tx * TN + 2*j;
#pragma unroll
            for (int e = 0; e < 2; e++) {
                int gn = gn0 + e;
                if (gn >= N) continue;
                float v = e ? v1 : v0;
                if (bias) v += bias[gn];
                if (ACT == 1) v = v / (1.f + fabsf(v));
                C[(long)gr * ldc + gn] = v;
            }
        }
    }
}

// -------------------- pointwise kernels -------------------------------------
__global__ void copy_xt(const float* __restrict__ x) {
    int i = blockIdx.x * blockDim.x + threadIdx.x;
    if (i < BB * TT) g_h0[(long)i * DIN + (DIN - 1)] = x[(long)i * DIN + (DIN - 1)];
}

__global__ void ln_kernel(const float* __restrict__ w, const float* __restrict__ b) {
    int row = blockIdx.x;
    const float* xr = g_h + (long)row * DM;
    float* orow = g_hn + (long)row * DM;
    int tid = threadIdx.x;
    float v[4], s = 0.f, s2 = 0.f;
#pragma unroll
    for (int i = 0; i < 4; i++) { v[i] = xr[tid + i * 128]; s += v[i]; s2 += v[i] * v[i]; }
#pragma unroll
    for (int o = 16; o > 0; o >>= 1) {
        s  += __shfl_down_sync(0xffffffffu, s, o);
        s2 += __shfl_down_sync(0xffffffffu, s2, o);
    }
    __shared__ float sh[8];
    int wid = tid >> 5, lane = tid & 31;
    if (!lane) { sh[wid] = s; sh[4 + wid] = s2; }
    __syncthreads();
    if (tid == 0) {
        float ts = 0.f, t2 = 0.f;
        for (int i = 0; i < 4; i++) { ts += sh[i]; t2 += sh[4 + i]; }
        sh[0] = ts; sh[4] = t2;
    }
    __syncthreads();
    float mu = sh[0] / (float)DM;
    float var = sh[4] / (float)DM - mu * mu;
    float inv = rsqrtf(var + EPSF);
#pragma unroll
    for (int i = 0; i < 4; i++) {
        int c = tid + i * 128;
        orow[c] = (v[i] - mu) * inv * w[c] + b[c];
    }
}

__global__ void conv_kernel(const float* __restrict__ conv_w,
                            const float* __restrict__ conv_b, int layer) {
    long idx = (long)blockIdx.x * blockDim.x + threadIdx.x;
    if (idx >= 2L * M2 * CONVD_) return;
    int c = (int)(idx % CONVD_);
    long r = idx / CONVD_;
    int dir = (int)(r / M2);
    int bt = (int)(r % M2);
    int b = bt / TO, t = bt % TO;
    int m = 2 * layer + dir;
    const float* wc = conv_w + ((long)m * CONVD_ + c) * DCONV;
    const float* zbase = g_zx + (long)dir * M2 * DINP + (long)b * TO * DINP;
    float s = conv_b[(long)m * CONVD_ + c];
#pragma unroll
    for (int j = 0; j < DCONV; j++) {
        int tt = dir ? (t + 3 - j) : (t - 3 + j);
        if (tt >= 0 && tt < TO) s += wc[j] * zbase[(long)tt * DINP + DI_ + c];
    }
    s = s / (1.f + expf(-s));
    g_xbc[(long)dir * M2 * CONVD_ + (long)bt * CONVD_ + c] = s;
}

__device__ __forceinline__ float softplusf(float x) {
    return x > 0.f ? x + log1pf(expf(-x)) : log1pf(expf(x));
}

// scan: grid (HH, BB, 2), 64 threads. Each thread owns head-dim p, all 64 states.
// dt/dA computed inline; one __syncthreads per step; register prefetch of t+1.
__global__ __launch_bounds__(64)
void scan_kernel(const float* __restrict__ Dp, const float* __restrict__ dtb,
                 const float* __restrict__ alog, int layer) {
    int h = blockIdx.x, b = blockIdx.y, dir = blockIdx.z;
    int m = 2 * layer + dir;
    int p = threadIdx.x;
    float Dh = Dp[m * HH + h];
    float dtbias = dtb[m * HH + h];
    float Aneg = -expf(alog[m * HH + h]);

    __shared__ __align__(16) float sB[2][64], sC[2][64];

    float st[64];
#pragma unroll
    for (int i = 0; i < 64; i++) st[i] = 0.f;

    const float* xbase = g_xbc + (long)dir * M2 * CONVD_ + (long)b * TO * CONVD_;
    float*       ybase = g_y   + (long)dir * M2 * DI_    + (long)b * TO * DI_;
    const float* zbase = g_zx  + ((long)dir * M2 + (long)b * TO) * DINP + DI_ + CONVD_ + h;

    int t0 = dir ? (TO - 1) : 0;
    const float* xr = xbase + (long)t0 * CONVD_;
    float rx = xr[h * 64 + p];
    float rB = xr[DI_ + p];
    float rC = xr[DI_ + DSTATE + p];
    float rraw = zbase[(long)t0 * DINP];

    for (int s_ = 0; s_ < TO; s_++) {
        int buf = s_ & 1;
        int t = dir ? (TO - 1 - s_) : s_;
        sB[buf][p] = rB;
        sC[buf][p] = rC;
        float xcur = rx, rawcur = rraw;
        __syncthreads();
        if (s_ + 1 < TO) {
            int t2 = dir ? (TO - 2 - s_) : (s_ + 1);
            const float* x2 = xbase + (long)t2 * CONVD_;
            rx = x2[h * 64 + p];
            rB = x2[DI_ + p];
            rC = x2[DI_ + DSTATE + p];
            rraw = zbase[(long)t2 * DINP];
        }
        float dt = softplusf(rawcur + dtbias);
        float da = expf(dt * Aneg);
        float dtx = dt * xcur;
        float y = Dh * xcur;
        const float4* B4 = reinterpret_cast<const float4*>(sB[buf]);
        const float4* C4 = reinterpret_cast<const float4*>(sC[buf]);
#pragma unroll
        for (int q = 0; q < 16; q++) {
            float4 bn = B4[q], cn = C4[q];
            st[4*q+0] = st[4*q+0] * da + dtx * bn.x;  y += st[4*q+0] * cn.x;
            st[4*q+1] = st[4*q+1] * da + dtx * bn.y;  y += st[4*q+1] * cn.y;
            st[4*q+2] = st[4*q+2] * da + dtx * bn.z;  y += st[4*q+2] * cn.z;
            st[4*q+3] = st[4*q+3] * da + dtx * bn.w;  y += st[4*q+3] * cn.w;
        }
        ybase[(long)t * DI_ + h * 64 + p] = y;
    }
}

__global__ void gnorm_kernel(const float* __restrict__ norm_w, int layer) {
    int row = blockIdx.x, dir = blockIdx.y;
    int m = 2 * layer + dir;
    const float* yrow = g_y + ((long)dir * M2 + row) * DI_;
    const float* zrow = g_zx + ((long)dir * M2 + row) * DINP;
    float* orow = g_y2 + (long)row * (2 * DI_) + (long)dir * DI_;
    int tid = threadIdx.x;
    float v[4], ss = 0.f;
#pragma unroll
    for (int i = 0; i < 4; i++) {
        int c = tid + i * 256;
        float z = zrow[c];
        float val = yrow[c] * (z / (1.f + expf(-z)));
        v[i] = val;
        ss += val * val;
    }
#pragma unroll
    for (int o = 16; o > 0; o >>= 1) ss += __shfl_down_sync(0xffffffffu, ss, o);
    __shared__ float sh[8];
    int wid = tid >> 5, lane = tid & 31;
    if (!lane) sh[wid] = ss;
    __syncthreads();
    if (tid == 0) { float tot = 0.f; for (int i = 0; i < 8; i++) tot += sh[i]; sh[0] = tot; }
    __syncthreads();
    float inv = rsqrtf(sh[0] / (float)DI_ + EPSF);
#pragma unroll
    for (int i = 0; i < 4; i++) {
        int c = tid + i * 256;
        orow[c] = v[i] * inv * norm_w[(long)m * DI_ + c];
    }
}

// -------------------- host orchestration ------------------------------------
#define SMEM128 (STAGES * (128 + 128) * SPITCH * 2)   /* 61440 */
#define SMEM64  (STAGES * (128 + 64)  * SPITCH * 2)   /* 46080 */

extern "C" void kernel_launch(void* const* d_in, const int* in_sizes, int n_in,
                              void* d_out, int out_size) {
    const float* x        = (const float*)d_in[0];
    const int*   day_idx  = (const int*)  d_in[1];
    const float* day_w    = (const float*)d_in[2];
    const float* day_b    = (const float*)d_in[3];
    const float* w1       = (const float*)d_in[4];
    const float* b1       = (const float*)d_in[5];
    const float* w2       = (const float*)d_in[6];
    const float* b2       = (const float*)d_in[7];
    const float* ln_w     = (const float*)d_in[8];
    const float* ln_b     = (const float*)d_in[9];
    const float* m_in_w   = (const float*)d_in[10];
    const float* m_conv_w = (const float*)d_in[11];
    const float* m_conv_b = (const float*)d_in[12];
    const float* m_dt     = (const float*)d_in[13];
    const float* m_Alog   = (const float*)d_in[14];
    const float* m_D      = (const float*)d_in[15];
    const float* m_norm_w = (const float*)d_in[16];
    const float* m_out_w  = (const float*)d_in[17];
    const float* out_w    = (const float*)d_in[18];
    const float* out_b    = (const float*)d_in[19];
    float* out = (float*)d_out;

    float *h0, *h1, *h, *hn, *zx, *y2;
    __nv_bfloat16 *a3, *w3;
    cudaGetSymbolAddress((void**)&h0, g_h0);
    cudaGetSymbolAddress((void**)&h1, g_h1);
    cudaGetSymbolAddress((void**)&h,  g_h);
    cudaGetSymbolAddress((void**)&hn, g_hn);
    cudaGetSymbolAddress((void**)&zx, g_zx);
    cudaGetSymbolAddress((void**)&y2, g_y2);
    cudaGetSymbolAddress((void**)&a3, g_a3);
    cudaGetSymbolAddress((void**)&w3, g_w3);

    cudaFuncSetAttribute(mma_gemm<128,1,0>, cudaFuncAttributeMaxDynamicSharedMemorySize, SMEM128);
    cudaFuncSetAttribute(mma_gemm<128,0,0>, cudaFuncAttributeMaxDynamicSharedMemorySize, SMEM128);
    cudaFuncSetAttribute(mma_gemm<64,0,0>,  cudaFuncAttributeMaxDynamicSharedMemorySize, SMEM64);
    cudaFuncSetAttribute(mma_gemm<64,0,1>,  cudaFuncAttributeMaxDynamicSharedMemorySize, SMEM64);

    // 1. day transform (EXACT fp32 f32x2 SIMT; per-batch weight) -> g_h0
    sgemm<128,128,8,8, 0,1><<<dim3(4, 16, BB), 256>>>(
        x, day_w, day_b, h0,
        TT, 512, 512, DIN, 512, DIN,
        (long)TT * DIN, (long)TT * DIN, 512L * 512L, 512L, day_idx);

    // 2. passthrough last channel
    copy_xt<<<(BB * TT + 255) / 256, 256>>>(x);

    // 3. w1 patch projection via mma (3-split bf16)
    cvt_w3<<<dim3(29, PROJD, 1), 256>>>(w1, w3, 7182, 7182, K3P_W1, 0, 0);
    cvt_a3<<<dim3(29, TO, BB), 256>>>(h0, a3, 7182, 4 * DIN, K3P_W1,
                                      (long)TT * DIN, (long)TO * K3P_W1);
    mma_gemm<128,1,0><<<dim3(PROJD / 128, 4, BB), 256, SMEM128>>>(
        a3, w3, b1, h1, TO, PROJD, K3P_W1, PROJD,
        (long)TO * K3P_W1, 0, (long)TO * PROJD);

    // 4. w2
    cvt_w3<<<dim3(16, DM, 1), 256>>>(w2, w3, PROJD, PROJD, K3P_W2, 0, 0);
    cvt_a3<<<dim3(16, M2, 1), 256>>>(h1, a3, PROJD, PROJD, K3P_W2, 0, 0);
    mma_gemm<64,0,0><<<dim3(DM / 64, 16, 1), 256, SMEM64>>>(
        a3, w3, b2, h, M2, DM, K3P_W2, DM, 0, 0, 0);

    // 5. layers
    for (int i = 0; i < LL; i++) {
        ln_kernel<<<M2, 128>>>(ln_w + (long)i * DM, ln_b + (long)i * DM);

        // in_proj: both directions (weight rows concatenated, z selects slice)
        cvt_w3<<<dim3(2, 2 * DINP, 1), 256>>>(
            m_in_w + (long)(2 * i) * DINP * DM, w3, DM, DM, K3P_IN, 0, 0);
        cvt_a3<<<dim3(2, M2, 1), 256>>>(hn, a3, DM, DM, K3P_IN, 0, 0);
        mma_gemm<128,0,0><<<dim3((DINP + 127) / 128, 16, 2), 256, SMEM128>>>(
            a3, w3, nullptr, zx, M2, DINP, K3P_IN, DINP,
            0, (long)DINP * K3P_IN, (long)M2 * DINP);

        conv_kernel<<<(int)((2L * M2 * CONVD_ + 255) / 256), 256>>>(m_conv_w, m_conv_b, i);
        scan_kernel<<<dim3(HH, BB, 2), 64>>>(m_D, m_dt, m_Alog, i);
        gnorm_kernel<<<dim3(M2, 2), 256>>>(m_norm_w, i);

        // out_proj: dirs fused along K (kh split), accumulate into h
        cvt_w3<<<dim3(8, DM, 1), 256>>>(
            m_out_w + (long)(2 * i) * DM * DI_, w3, 2 * DI_, DI_, K3P_OUT,
            DI_, (long)DM * DI_);
        cvt_a3<<<dim3(8, M2, 1), 256>>>(y2, a3, 2 * DI_, 2 * DI_, K3P_OUT, 0, 0);
        mma_gemm<64,0,1><<<dim3(DM / 64, 16, 1), 256, SMEM64>>>(
            a3, w3, nullptr, h, M2, DM, K3P_OUT, DM, 0, 0, 0);
    }

    // 6. classifier (small; f32x2 SIMT)
    sgemm<64,64,4,4, 1,0><<<dim3(1, (M2 + 63) / 64, 1), 256>>>(
        h, out_w, out_b, out, M2, 41, DM, DM, DM, 41,
        0, 0, 0, 0, nullptr);
}